// round 10
// baseline (speedup 1.0000x reference)
#include <cuda_runtime.h>
#include <cstdint>
#include <cmath>

#define N_NODES 16384
#define N_EDGES 262144
#define N_GRAPHS 16
#define IN_CH 128
#define HID_CH 256
#define LAT 64

// ---- output layout (tuple flattened, all fp32) ----
// z_node  [16384,64]   @ 0
// z_graph [16,64]      @ 1048576
// x_hat   [16384,128]  @ 1049600
// a_hat   [16384,16384]@ 3146752

// ---- device scratch ----
__device__ float g_dinv[N_NODES];                        // degree, then rsqrt(degree)
__device__ __align__(16) float g_agg[N_NODES * IN_CH];   // sum incoming + self
__device__ __align__(16) float g_h  [N_NODES * HID_CH];  // relu hidden
__device__ __align__(16) float g_xg [N_GRAPHS * IN_CH];  // decoded per-graph row

__device__ __forceinline__ uint32_t f2tf32(float f) {
    uint32_t u;
    asm("cvt.rna.tf32.f32 %0, %1;" : "=r"(u) : "f"(f));
    return u;
}
__device__ __forceinline__ float fsig(float x) {
    float t;
    asm("tanh.approx.f32 %0, %1;" : "=f"(t) : "f"(x * 0.5f));
    return fmaf(t, 0.5f, 0.5f);
}
#define MMA_TF32(acc, a, b)                                                    \
    asm volatile(                                                              \
        "mma.sync.aligned.m16n8k8.row.col.f32.tf32.tf32.f32 "                  \
        "{%0,%1,%2,%3}, {%4,%5,%6,%7}, {%8,%9}, {%0,%1,%2,%3};"                \
        : "+f"(acc[0]), "+f"(acc[1]), "+f"(acc[2]), "+f"(acc[3])               \
        : "r"(a[0]), "r"(a[1]), "r"(a[2]), "r"(a[3]), "r"(b[0]), "r"(b[1]))

#define TLD 68   // tf32 smem pitch (uint32)

// ============================================================
__global__ void k_init() {
    int i = blockIdx.x * blockDim.x + threadIdx.x;
    if (i < N_NODES) g_dinv[i] = 1.0f;               // self-loop degree
}

__global__ void k_degree(const int* __restrict__ ei) {
    int e = blockIdx.x * blockDim.x + threadIdx.x;
    if (e < N_EDGES) atomicAdd(&g_dinv[ei[N_EDGES + e]], 1.0f);
}

// d = rsqrt(deg); agg init = d*x (self-loop term); store d back
__global__ void k_scale(const float4* __restrict__ x4) {
    int idx = blockIdx.x * blockDim.x + threadIdx.x; // < N_NODES*32
    int node = idx >> 5;
    int lane = idx & 31;
    float d = rsqrtf(g_dinv[node]);
    float4 v = x4[idx];
    v.x *= d; v.y *= d; v.z *= d; v.w *= d;
    ((float4*)g_agg)[idx] = v;
    if (lane == 0) g_dinv[node] = d;
}

// one warp per edge: 32 lanes x float4 = 128 ch; dinv applied on the fly
__global__ void k_scatter(const int* __restrict__ ei, const float4* __restrict__ x4) {
    int gid = blockIdx.x * blockDim.x + threadIdx.x;
    int e = gid >> 5;
    int lane = gid & 31;
    if (e >= N_EDGES) return;
    int r = ei[e];
    int c = ei[N_EDGES + e];
    float d = g_dinv[r];
    float4 v = x4[r * 32 + lane];
    v.x *= d; v.y *= d; v.z *= d; v.w *= d;
    atomicAdd((float4*)(g_agg + c * IN_CH + lane * 4), v);
}

// ============================================================
// GEMM1 (tf32 MMA): h = relu( (dinv.*agg)[16384,128] @ gcn_w[256,128]^T + b )
// block 128x128, 8 warps (2x4), warp 64x32, K chunked 64 (2 chunks)
// ============================================================
__global__ __launch_bounds__(256, 2) void k_gemm1(const float* __restrict__ W,
                                                  const float* __restrict__ bias) {
    extern __shared__ uint32_t smbuf[];
    uint32_t* As = smbuf;               // [128][TLD]
    uint32_t* Bs = smbuf + 128 * TLD;   // [128][TLD]
    int m0 = blockIdx.y * 128, n0 = blockIdx.x * 128;
    int tid = threadIdx.x;
    int warp = tid >> 5, lane = tid & 31;
    int wm = (warp >> 2) * 64, wn = (warp & 3) * 32;
    int gp = lane >> 2, tq = lane & 3;

    float acc[4][4][4];
#pragma unroll
    for (int mt = 0; mt < 4; mt++)
#pragma unroll
        for (int nt = 0; nt < 4; nt++)
#pragma unroll
            for (int r = 0; r < 4; r++) acc[mt][nt][r] = 0.0f;

#pragma unroll
    for (int kc = 0; kc < IN_CH; kc += 64) {
        if (kc) __syncthreads();
#pragma unroll
        for (int it = 0; it < 8; ++it) {
            int idx = tid + it * 256;       // 2048 float4 per 128x64 tile
            int row = idx >> 4, q = idx & 15;
            float4 va = ((const float4*)g_agg)[(m0 + row) * (IN_CH / 4) + (kc >> 2) + q];
            float d = g_dinv[m0 + row];
            As[row * TLD + q * 4 + 0] = f2tf32(va.x * d);
            As[row * TLD + q * 4 + 1] = f2tf32(va.y * d);
            As[row * TLD + q * 4 + 2] = f2tf32(va.z * d);
            As[row * TLD + q * 4 + 3] = f2tf32(va.w * d);
            float4 vb = ((const float4*)W)[(n0 + row) * (IN_CH / 4) + (kc >> 2) + q];
            Bs[row * TLD + q * 4 + 0] = f2tf32(vb.x);
            Bs[row * TLD + q * 4 + 1] = f2tf32(vb.y);
            Bs[row * TLD + q * 4 + 2] = f2tf32(vb.z);
            Bs[row * TLD + q * 4 + 3] = f2tf32(vb.w);
        }
        __syncthreads();
#pragma unroll
        for (int ks = 0; ks < 8; ++ks) {
            int kb = ks * 8;
            uint32_t a[4][4], b[4][2];
#pragma unroll
            for (int mt = 0; mt < 4; ++mt) {
                int r0 = wm + mt * 16 + gp;
                a[mt][0] = As[r0 * TLD + kb + tq];
                a[mt][1] = As[(r0 + 8) * TLD + kb + tq];
                a[mt][2] = As[r0 * TLD + kb + tq + 4];
                a[mt][3] = As[(r0 + 8) * TLD + kb + tq + 4];
            }
#pragma unroll
            for (int nt = 0; nt < 4; ++nt) {
                int c0 = wn + nt * 8 + gp;
                b[nt][0] = Bs[c0 * TLD + kb + tq];
                b[nt][1] = Bs[c0 * TLD + kb + tq + 4];
            }
#pragma unroll
            for (int mt = 0; mt < 4; ++mt)
#pragma unroll
                for (int nt = 0; nt < 4; ++nt) MMA_TF32(acc[mt][nt], a[mt], b[nt]);
        }
    }

#pragma unroll
    for (int mt = 0; mt < 4; ++mt)
#pragma unroll
        for (int nt = 0; nt < 4; ++nt) {
            int row = m0 + wm + mt * 16 + gp;
            int col = n0 + wn + nt * 8 + tq * 2;
            float b0 = bias[col], b1 = bias[col + 1];
            *(float2*)(g_h + row * HID_CH + col) =
                make_float2(fmaxf(acc[mt][nt][0] + b0, 0.0f), fmaxf(acc[mt][nt][1] + b1, 0.0f));
            *(float2*)(g_h + (row + 8) * HID_CH + col) =
                make_float2(fmaxf(acc[mt][nt][2] + b0, 0.0f), fmaxf(acc[mt][nt][3] + b1, 0.0f));
        }
}

// ============================================================
// GEMM2 (tf32 MMA): z_node = h[16384,256] @ lin_w[64,256]^T + lin_b
// block 128x64, 8 warps (4x2), warp 32x32, K chunked 64 (4 chunks)
// ============================================================
__global__ __launch_bounds__(256) void k_gemm2(const float* __restrict__ W,
                                               const float* __restrict__ bias,
                                               float* __restrict__ Z) {
    extern __shared__ uint32_t smbuf[];
    uint32_t* As = smbuf;               // [128][TLD]
    uint32_t* Bs = smbuf + 128 * TLD;   // [64][TLD]
    int m0 = blockIdx.x * 128;
    int tid = threadIdx.x;
    int warp = tid >> 5, lane = tid & 31;
    int wm = (warp >> 1) * 32, wn = (warp & 1) * 32;
    int gp = lane >> 2, tq = lane & 3;

    float acc[2][4][4];
#pragma unroll
    for (int mt = 0; mt < 2; mt++)
#pragma unroll
        for (int nt = 0; nt < 4; nt++)
#pragma unroll
            for (int r = 0; r < 4; r++) acc[mt][nt][r] = 0.0f;

#pragma unroll
    for (int kc = 0; kc < HID_CH; kc += 64) {
        if (kc) __syncthreads();
#pragma unroll
        for (int it = 0; it < 8; ++it) {
            int idx = tid + it * 256;       // A: 2048 float4
            int row = idx >> 4, q = idx & 15;
            float4 va = ((const float4*)g_h)[(m0 + row) * (HID_CH / 4) + (kc >> 2) + q];
            As[row * TLD + q * 4 + 0] = f2tf32(va.x);
            As[row * TLD + q * 4 + 1] = f2tf32(va.y);
            As[row * TLD + q * 4 + 2] = f2tf32(va.z);
            As[row * TLD + q * 4 + 3] = f2tf32(va.w);
        }
#pragma unroll
        for (int it = 0; it < 4; ++it) {
            int idx = tid + it * 256;       // B: 1024 float4
            int row = idx >> 4, q = idx & 15;
            float4 vb = ((const float4*)W)[row * (HID_CH / 4) + (kc >> 2) + q];
            Bs[row * TLD + q * 4 + 0] = f2tf32(vb.x);
            Bs[row * TLD + q * 4 + 1] = f2tf32(vb.y);
            Bs[row * TLD + q * 4 + 2] = f2tf32(vb.z);
            Bs[row * TLD + q * 4 + 3] = f2tf32(vb.w);
        }
        __syncthreads();
#pragma unroll
        for (int ks = 0; ks < 8; ++ks) {
            int kb = ks * 8;
            uint32_t a[2][4], b[4][2];
#pragma unroll
            for (int mt = 0; mt < 2; ++mt) {
                int r0 = wm + mt * 16 + gp;
                a[mt][0] = As[r0 * TLD + kb + tq];
                a[mt][1] = As[(r0 + 8) * TLD + kb + tq];
                a[mt][2] = As[r0 * TLD + kb + tq + 4];
                a[mt][3] = As[(r0 + 8) * TLD + kb + tq + 4];
            }
#pragma unroll
            for (int nt = 0; nt < 4; ++nt) {
                int c0 = wn + nt * 8 + gp;
                b[nt][0] = Bs[c0 * TLD + kb + tq];
                b[nt][1] = Bs[c0 * TLD + kb + tq + 4];
            }
#pragma unroll
            for (int mt = 0; mt < 2; ++mt)
#pragma unroll
                for (int nt = 0; nt < 4; ++nt) MMA_TF32(acc[mt][nt], a[mt], b[nt]);
        }
    }

#pragma unroll
    for (int mt = 0; mt < 2; ++mt)
#pragma unroll
        for (int nt = 0; nt < 4; ++nt) {
            int row = m0 + wm + mt * 16 + gp;
            int col = wn + nt * 8 + tq * 2;
            float b0 = bias[col], b1 = bias[col + 1];
            *(float2*)(Z + row * LAT + col) =
                make_float2(acc[mt][nt][0] + b0, acc[mt][nt][1] + b1);
            *(float2*)(Z + (row + 8) * LAT + col) =
                make_float2(acc[mt][nt][2] + b0, acc[mt][nt][3] + b1);
        }
}

// ============================================================
// fused pool + z_graph + decoded graph rows (batch sorted -> binary search)
// ============================================================
__global__ void k_poolfused(const float* __restrict__ Z, const int* __restrict__ batch,
                            float* __restrict__ z_graph,
                            const float* __restrict__ dec_w, const float* __restrict__ dec_b) {
    __shared__ float red[4][LAT];
    __shared__ float zg[LAT];
    int g = blockIdx.x;
    int tid = threadIdx.x;
    int k = tid & 63, sub = tid >> 6;

    int lo = 0, hi = N_NODES;
    while (lo < hi) { int mid = (lo + hi) >> 1; if (batch[mid] < g) lo = mid + 1; else hi = mid; }
    int start = lo;
    hi = N_NODES;
    while (lo < hi) { int mid = (lo + hi) >> 1; if (batch[mid] < g + 1) lo = mid + 1; else hi = mid; }
    int end = lo;

    float acc = 0.0f;
    for (int n = start + sub; n < end; n += 4) acc += Z[n * LAT + k];
    red[sub][k] = acc;
    __syncthreads();
    if (sub == 0) {
        float s = red[0][k] + red[1][k] + red[2][k] + red[3][k];
        float zv = s / fmaxf((float)(end - start), 1.0f);
        z_graph[g * LAT + k] = zv;
        zg[k] = zv;
    }
    __syncthreads();
    if (tid < IN_CH) {
        float s = dec_b[tid];
#pragma unroll
        for (int kk = 0; kk < LAT; kk++) s = fmaf(zg[kk], dec_w[tid * LAT + kk], s);
        g_xg[g * IN_CH + tid] = s;
    }
}

__global__ void k_xhat(const int* __restrict__ batch, float* __restrict__ x_hat) {
    int idx = blockIdx.x * blockDim.x + threadIdx.x;  // < N_NODES*32
    int node = idx >> 5;
    int g = batch[node];
    ((float4*)x_hat)[idx] = ((const float4*)g_xg)[g * 32 + (idx & 31)];
}

// ============================================================
// a_hat = sigmoid(Z @ Z^T): symmetric, upper-tri tiles only.
// Direct orientation: streaming STG.64 from registers.
// Mirror orientation: smem transpose -> streaming STG.128.
// ============================================================
#define AH_TLD 132        // transpose staging pitch (float)
#define AH_NTILE 128
#define AH_NBLK (AH_NTILE * (AH_NTILE + 1) / 2)   // 8256

__global__ __launch_bounds__(256, 2) void k_ahat(const float* __restrict__ Z,
                                                 float* __restrict__ out) {
    extern __shared__ uint32_t smbuf[];
    uint32_t* As = smbuf;                 // [128][TLD]
    uint32_t* Bs = smbuf + 128 * TLD;     // [128][TLD]

    // decode linear block -> (bm<=bn): L = bn*(bn+1)/2 + bm
    int L = blockIdx.x;
    int bn = (int)((sqrtf(8.0f * (float)L + 1.0f) - 1.0f) * 0.5f);
    while ((bn + 1) * (bn + 2) / 2 <= L) bn++;
    while (bn * (bn + 1) / 2 > L) bn--;
    int bm = L - bn * (bn + 1) / 2;

    int tid = threadIdx.x;
    const float4* Z4 = (const float4*)Z;

#pragma unroll
    for (int it = 0; it < 8; ++it) {
        int idx = tid + it * 256;       // 2048 float4 per tile
        int row = idx >> 4, q = idx & 15;
        float4 va = Z4[(bm * 128 + row) * 16 + q];
        As[row * TLD + q * 4 + 0] = f2tf32(va.x);
        As[row * TLD + q * 4 + 1] = f2tf32(va.y);
        As[row * TLD + q * 4 + 2] = f2tf32(va.z);
        As[row * TLD + q * 4 + 3] = f2tf32(va.w);
        float4 vb = Z4[(bn * 128 + row) * 16 + q];
        Bs[row * TLD + q * 4 + 0] = f2tf32(vb.x);
        Bs[row * TLD + q * 4 + 1] = f2tf32(vb.y);
        Bs[row * TLD + q * 4 + 2] = f2tf32(vb.z);
        Bs[row * TLD + q * 4 + 3] = f2tf32(vb.w);
    }
    __syncthreads();

    int warp = tid >> 5, lane = tid & 31;
    int wm = (warp >> 2) * 64;
    int wn = (warp & 3) * 32;
    int gp = lane >> 2, tq = lane & 3;

    float acc[4][4][4];
#pragma unroll
    for (int mt = 0; mt < 4; mt++)
#pragma unroll
        for (int nt = 0; nt < 4; nt++)
#pragma unroll
            for (int r = 0; r < 4; r++) acc[mt][nt][r] = 0.0f;

#pragma unroll
    for (int ks = 0; ks < 8; ++ks) {
        int kb = ks * 8;
        uint32_t a[4][4], b[4][2];
#pragma unroll
        for (int mt = 0; mt < 4; ++mt) {
            int r0 = wm + mt * 16 + gp;
            a[mt][0] = As[r0 * TLD + kb + tq];
            a[mt][1] = As[(r0 + 8) * TLD + kb + tq];
            a[mt][2] = As[r0 * TLD + kb + tq + 4];
            a[mt][3] = As[(r0 + 8) * TLD + kb + tq + 4];
        }
#pragma unroll
        for (int nt = 0; nt < 4; ++nt) {
            int c0 = wn + nt * 8 + gp;
            b[nt][0] = Bs[c0 * TLD + kb + tq];
            b[nt][1] = Bs[c0 * TLD + kb + tq + 4];
        }
#pragma unroll
        for (int mt = 0; mt < 4; ++mt)
#pragma unroll
            for (int nt = 0; nt < 4; ++nt) MMA_TF32(acc[mt][nt], a[mt], b[nt]);
    }

    // sigmoid in registers, streaming STG.64 store of (bm,bn) tile
#pragma unroll
    for (int mt = 0; mt < 4; ++mt)
#pragma unroll
        for (int nt = 0; nt < 4; ++nt) {
#pragma unroll
            for (int r = 0; r < 4; ++r) acc[mt][nt][r] = fsig(acc[mt][nt][r]);
            int row = bm * 128 + wm + mt * 16 + gp;
            int col = bn * 128 + wn + nt * 8 + tq * 2;
            __stcs((float2*)(out + (size_t)row * N_NODES + col),
                   make_float2(acc[mt][nt][0], acc[mt][nt][1]));
            __stcs((float2*)(out + (size_t)(row + 8) * N_NODES + col),
                   make_float2(acc[mt][nt][2], acc[mt][nt][3]));
        }

    // mirror tile: transpose through smem (reuse As/Bs), streaming STG.128
    if (bm != bn) {
        __syncthreads();
        float* S = (float*)smbuf;         // [128][AH_TLD], 67584 B
#pragma unroll
        for (int mt = 0; mt < 4; ++mt)
#pragma unroll
            for (int nt = 0; nt < 4; ++nt) {
                int rl = wm + mt * 16 + gp;
                int cl = wn + nt * 8 + tq * 2;
                S[cl * AH_TLD + rl]           = acc[mt][nt][0];
                S[(cl + 1) * AH_TLD + rl]     = acc[mt][nt][1];
                S[cl * AH_TLD + rl + 8]       = acc[mt][nt][2];
                S[(cl + 1) * AH_TLD + rl + 8] = acc[mt][nt][3];
            }
        __syncthreads();
#pragma unroll
        for (int it = 0; it < 16; ++it) {
            int idx = tid + it * 256;     // 4096 float4
            int rt = idx >> 5, q = idx & 31;
            float4 w = *(const float4*)(S + rt * AH_TLD + q * 4);
            __stcs((float4*)(out + (size_t)(bn * 128 + rt) * N_NODES + bm * 128 + q * 4), w);
        }
    }
}

// ============================================================
// launch: pool+xhat forked to a side stream, overlapped with k_ahat
// ============================================================
extern "C" void kernel_launch(void* const* d_in, const int* in_sizes, int n_in,
                              void* d_out, int out_size) {
    const float* x     = (const float*)d_in[0];
    const int*   ei    = (const int*)d_in[1];    // int32
    const int*   batch = (const int*)d_in[2];    // int32, sorted
    const float* gcn_w = (const float*)d_in[3];
    const float* gcn_b = (const float*)d_in[4];
    const float* lin_w = (const float*)d_in[5];
    const float* lin_b = (const float*)d_in[6];
    const float* dec_w = (const float*)d_in[7];
    const float* dec_b = (const float*)d_in[8];

    float* out     = (float*)d_out;
    float* z_node  = out;
    float* z_graph = out + 1048576;
    float* x_hat   = out + 1049600;
    float* a_hat   = out + 3146752;

    static cudaStream_t s2 = nullptr;
    static cudaEvent_t eFork = nullptr, eJoin = nullptr;
    if (!s2) {
        cudaStreamCreateWithFlags(&s2, cudaStreamNonBlocking);
        cudaEventCreateWithFlags(&eFork, cudaEventDisableTiming);
        cudaEventCreateWithFlags(&eJoin, cudaEventDisableTiming);
        const int SM2T = 2 * 128 * TLD * 4;
        const int SMG2 = (128 + 64) * TLD * 4;
        cudaFuncSetAttribute(k_ahat,  cudaFuncAttributeMaxDynamicSharedMemorySize, SM2T);
        cudaFuncSetAttribute(k_gemm1, cudaFuncAttributeMaxDynamicSharedMemorySize, SM2T);
        cudaFuncSetAttribute(k_gemm2, cudaFuncAttributeMaxDynamicSharedMemorySize, SMG2);
    }
    const int SMEM_2T = 2 * 128 * TLD * 4;       // 69632 B
    const int SMEM_G2 = (128 + 64) * TLD * 4;    // 52224 B

    k_init<<<64, 256>>>();
    k_degree<<<1024, 256>>>(ei);
    k_scale<<<2048, 256>>>((const float4*)x);
    k_scatter<<<32768, 256>>>(ei, (const float4*)x);
    k_gemm1<<<dim3(2, 128), 256, SMEM_2T>>>(gcn_w, gcn_b);
    k_gemm2<<<128, 256, SMEM_G2>>>(lin_w, lin_b, z_node);

    // fork: pool + xhat run on s2 concurrently with k_ahat on the main stream
    cudaEventRecord(eFork, 0);
    cudaStreamWaitEvent(s2, eFork, 0);
    k_poolfused<<<N_GRAPHS, 256, 0, s2>>>(z_node, batch, z_graph, dec_w, dec_b);
    k_xhat<<<2048, 256, 0, s2>>>(batch, x_hat);
    cudaEventRecord(eJoin, s2);

    k_ahat<<<AH_NBLK, 256, SMEM_2T>>>(z_node, a_hat);

    // join
    cudaStreamWaitEvent(0, eJoin, 0);
}

// round 11
// speedup vs baseline: 1.5243x; 1.5243x over previous
#include <cuda_runtime.h>
#include <cstdint>
#include <cmath>

#define N_NODES 16384
#define N_EDGES 262144
#define N_GRAPHS 16
#define IN_CH 128
#define HID_CH 256
#define LAT 64

// ---- output layout (tuple flattened, all fp32) ----
// z_node  [16384,64]   @ 0
// z_graph [16,64]      @ 1048576
// x_hat   [16384,128]  @ 1049600
// a_hat   [16384,16384]@ 3146752

// NOTE: k_scatter is the in-band environment probe: fixed work, history
// 32.3-33.1us on healthy holds. Normalize total dur by (scatter/33) before
// comparing across rounds.

// ---- device scratch ----
__device__ float g_dinv[N_NODES];                        // degree, then rsqrt(degree)
__device__ __align__(16) float g_agg[N_NODES * IN_CH];   // sum incoming + self
__device__ __align__(16) float g_h  [N_NODES * HID_CH];  // relu hidden
__device__ __align__(16) float g_xg [N_GRAPHS * IN_CH];  // decoded per-graph row

__device__ __forceinline__ uint32_t f2tf32(float f) {
    uint32_t u;
    asm("cvt.rna.tf32.f32 %0, %1;" : "=r"(u) : "f"(f));
    return u;
}
__device__ __forceinline__ float fsig(float x) {
    float t;
    asm("tanh.approx.f32 %0, %1;" : "=f"(t) : "f"(x * 0.5f));
    return fmaf(t, 0.5f, 0.5f);
}
#define MMA_TF32(acc, a, b)                                                    \
    asm volatile(                                                              \
        "mma.sync.aligned.m16n8k8.row.col.f32.tf32.tf32.f32 "                  \
        "{%0,%1,%2,%3}, {%4,%5,%6,%7}, {%8,%9}, {%0,%1,%2,%3};"                \
        : "+f"(acc[0]), "+f"(acc[1]), "+f"(acc[2]), "+f"(acc[3])               \
        : "r"(a[0]), "r"(a[1]), "r"(a[2]), "r"(a[3]), "r"(b[0]), "r"(b[1]))

#define TLD 68   // tf32 smem pitch (uint32)

// ============================================================
__global__ void k_init() {
    int i = blockIdx.x * blockDim.x + threadIdx.x;
    if (i < N_NODES) g_dinv[i] = 1.0f;               // self-loop degree
}

__global__ void k_degree(const int* __restrict__ ei) {
    int e = blockIdx.x * blockDim.x + threadIdx.x;
    if (e < N_EDGES) atomicAdd(&g_dinv[ei[N_EDGES + e]], 1.0f);
}

// d = rsqrt(deg); agg init = d*x (self-loop term); store d back
__global__ void k_scale(const float4* __restrict__ x4) {
    int idx = blockIdx.x * blockDim.x + threadIdx.x; // < N_NODES*32
    int node = idx >> 5;
    int lane = idx & 31;
    float d = rsqrtf(g_dinv[node]);
    float4 v = x4[idx];
    v.x *= d; v.y *= d; v.z *= d; v.w *= d;
    ((float4*)g_agg)[idx] = v;
    if (lane == 0) g_dinv[node] = d;
}

// one warp per edge: 32 lanes x float4 = 128 ch; dinv applied on the fly
__global__ void k_scatter(const int* __restrict__ ei, const float4* __restrict__ x4) {
    int gid = blockIdx.x * blockDim.x + threadIdx.x;
    int e = gid >> 5;
    int lane = gid & 31;
    if (e >= N_EDGES) return;
    int r = ei[e];
    int c = ei[N_EDGES + e];
    float d = g_dinv[r];
    float4 v = x4[r * 32 + lane];
    v.x *= d; v.y *= d; v.z *= d; v.w *= d;
    atomicAdd((float4*)(g_agg + c * IN_CH + lane * 4), v);
}

// ============================================================
// GEMM1 (tf32 MMA): h = relu( (dinv.*agg)[16384,128] @ gcn_w[256,128]^T + b )
// block 128x128, 8 warps (2x4), warp 64x32, K chunked 64 (2 chunks)
// ============================================================
__global__ __launch_bounds__(256, 2) void k_gemm1(const float* __restrict__ W,
                                                  const float* __restrict__ bias) {
    extern __shared__ uint32_t smbuf[];
    uint32_t* As = smbuf;               // [128][TLD]
    uint32_t* Bs = smbuf + 128 * TLD;   // [128][TLD]
    int m0 = blockIdx.y * 128, n0 = blockIdx.x * 128;
    int tid = threadIdx.x;
    int warp = tid >> 5, lane = tid & 31;
    int wm = (warp >> 2) * 64, wn = (warp & 3) * 32;
    int gp = lane >> 2, tq = lane & 3;

    float acc[4][4][4];
#pragma unroll
    for (int mt = 0; mt < 4; mt++)
#pragma unroll
        for (int nt = 0; nt < 4; nt++)
#pragma unroll
            for (int r = 0; r < 4; r++) acc[mt][nt][r] = 0.0f;

#pragma unroll
    for (int kc = 0; kc < IN_CH; kc += 64) {
        if (kc) __syncthreads();
#pragma unroll
        for (int it = 0; it < 8; ++it) {
            int idx = tid + it * 256;       // 2048 float4 per 128x64 tile
            int row = idx >> 4, q = idx & 15;
            float4 va = ((const float4*)g_agg)[(m0 + row) * (IN_CH / 4) + (kc >> 2) + q];
            float d = g_dinv[m0 + row];
            As[row * TLD + q * 4 + 0] = f2tf32(va.x * d);
            As[row * TLD + q * 4 + 1] = f2tf32(va.y * d);
            As[row * TLD + q * 4 + 2] = f2tf32(va.z * d);
            As[row * TLD + q * 4 + 3] = f2tf32(va.w * d);
            float4 vb = ((const float4*)W)[(n0 + row) * (IN_CH / 4) + (kc >> 2) + q];
            Bs[row * TLD + q * 4 + 0] = f2tf32(vb.x);
            Bs[row * TLD + q * 4 + 1] = f2tf32(vb.y);
            Bs[row * TLD + q * 4 + 2] = f2tf32(vb.z);
            Bs[row * TLD + q * 4 + 3] = f2tf32(vb.w);
        }
        __syncthreads();
#pragma unroll
        for (int ks = 0; ks < 8; ++ks) {
            int kb = ks * 8;
            uint32_t a[4][4], b[4][2];
#pragma unroll
            for (int mt = 0; mt < 4; ++mt) {
                int r0 = wm + mt * 16 + gp;
                a[mt][0] = As[r0 * TLD + kb + tq];
                a[mt][1] = As[(r0 + 8) * TLD + kb + tq];
                a[mt][2] = As[r0 * TLD + kb + tq + 4];
                a[mt][3] = As[(r0 + 8) * TLD + kb + tq + 4];
            }
#pragma unroll
            for (int nt = 0; nt < 4; ++nt) {
                int c0 = wn + nt * 8 + gp;
                b[nt][0] = Bs[c0 * TLD + kb + tq];
                b[nt][1] = Bs[c0 * TLD + kb + tq + 4];
            }
#pragma unroll
            for (int mt = 0; mt < 4; ++mt)
#pragma unroll
                for (int nt = 0; nt < 4; ++nt) MMA_TF32(acc[mt][nt], a[mt], b[nt]);
        }
    }

#pragma unroll
    for (int mt = 0; mt < 4; ++mt)
#pragma unroll
        for (int nt = 0; nt < 4; ++nt) {
            int row = m0 + wm + mt * 16 + gp;
            int col = n0 + wn + nt * 8 + tq * 2;
            float b0 = bias[col], b1 = bias[col + 1];
            *(float2*)(g_h + row * HID_CH + col) =
                make_float2(fmaxf(acc[mt][nt][0] + b0, 0.0f), fmaxf(acc[mt][nt][1] + b1, 0.0f));
            *(float2*)(g_h + (row + 8) * HID_CH + col) =
                make_float2(fmaxf(acc[mt][nt][2] + b0, 0.0f), fmaxf(acc[mt][nt][3] + b1, 0.0f));
        }
}

// ============================================================
// GEMM2 (tf32 MMA): z_node = h[16384,256] @ lin_w[64,256]^T + lin_b
// block 128x64, 8 warps (4x2), warp 32x32, K chunked 64 (4 chunks)
// ============================================================
__global__ __launch_bounds__(256) void k_gemm2(const float* __restrict__ W,
                                               const float* __restrict__ bias,
                                               float* __restrict__ Z) {
    extern __shared__ uint32_t smbuf[];
    uint32_t* As = smbuf;               // [128][TLD]
    uint32_t* Bs = smbuf + 128 * TLD;   // [64][TLD]
    int m0 = blockIdx.x * 128;
    int tid = threadIdx.x;
    int warp = tid >> 5, lane = tid & 31;
    int wm = (warp >> 1) * 32, wn = (warp & 1) * 32;
    int gp = lane >> 2, tq = lane & 3;

    float acc[2][4][4];
#pragma unroll
    for (int mt = 0; mt < 2; mt++)
#pragma unroll
        for (int nt = 0; nt < 4; nt++)
#pragma unroll
            for (int r = 0; r < 4; r++) acc[mt][nt][r] = 0.0f;

#pragma unroll
    for (int kc = 0; kc < HID_CH; kc += 64) {
        if (kc) __syncthreads();
#pragma unroll
        for (int it = 0; it < 8; ++it) {
            int idx = tid + it * 256;       // A: 2048 float4
            int row = idx >> 4, q = idx & 15;
            float4 va = ((const float4*)g_h)[(m0 + row) * (HID_CH / 4) + (kc >> 2) + q];
            As[row * TLD + q * 4 + 0] = f2tf32(va.x);
            As[row * TLD + q * 4 + 1] = f2tf32(va.y);
            As[row * TLD + q * 4 + 2] = f2tf32(va.z);
            As[row * TLD + q * 4 + 3] = f2tf32(va.w);
        }
#pragma unroll
        for (int it = 0; it < 4; ++it) {
            int idx = tid + it * 256;       // B: 1024 float4
            int row = idx >> 4, q = idx & 15;
            float4 vb = ((const float4*)W)[row * (HID_CH / 4) + (kc >> 2) + q];
            Bs[row * TLD + q * 4 + 0] = f2tf32(vb.x);
            Bs[row * TLD + q * 4 + 1] = f2tf32(vb.y);
            Bs[row * TLD + q * 4 + 2] = f2tf32(vb.z);
            Bs[row * TLD + q * 4 + 3] = f2tf32(vb.w);
        }
        __syncthreads();
#pragma unroll
        for (int ks = 0; ks < 8; ++ks) {
            int kb = ks * 8;
            uint32_t a[2][4], b[4][2];
#pragma unroll
            for (int mt = 0; mt < 2; ++mt) {
                int r0 = wm + mt * 16 + gp;
                a[mt][0] = As[r0 * TLD + kb + tq];
                a[mt][1] = As[(r0 + 8) * TLD + kb + tq];
                a[mt][2] = As[r0 * TLD + kb + tq + 4];
                a[mt][3] = As[(r0 + 8) * TLD + kb + tq + 4];
            }
#pragma unroll
            for (int nt = 0; nt < 4; ++nt) {
                int c0 = wn + nt * 8 + gp;
                b[nt][0] = Bs[c0 * TLD + kb + tq];
                b[nt][1] = Bs[c0 * TLD + kb + tq + 4];
            }
#pragma unroll
            for (int mt = 0; mt < 2; ++mt)
#pragma unroll
                for (int nt = 0; nt < 4; ++nt) MMA_TF32(acc[mt][nt], a[mt], b[nt]);
        }
    }

#pragma unroll
    for (int mt = 0; mt < 2; ++mt)
#pragma unroll
        for (int nt = 0; nt < 4; ++nt) {
            int row = m0 + wm + mt * 16 + gp;
            int col = wn + nt * 8 + tq * 2;
            float b0 = bias[col], b1 = bias[col + 1];
            *(float2*)(Z + row * LAT + col) =
                make_float2(acc[mt][nt][0] + b0, acc[mt][nt][1] + b1);
            *(float2*)(Z + (row + 8) * LAT + col) =
                make_float2(acc[mt][nt][2] + b0, acc[mt][nt][3] + b1);
        }
}

// ============================================================
// fused pool + z_graph + decoded graph rows (batch sorted -> binary search)
// ============================================================
__global__ void k_poolfused(const float* __restrict__ Z, const int* __restrict__ batch,
                            float* __restrict__ z_graph,
                            const float* __restrict__ dec_w, const float* __restrict__ dec_b) {
    __shared__ float red[4][LAT];
    __shared__ float zg[LAT];
    int g = blockIdx.x;
    int tid = threadIdx.x;
    int k = tid & 63, sub = tid >> 6;

    int lo = 0, hi = N_NODES;
    while (lo < hi) { int mid = (lo + hi) >> 1; if (batch[mid] < g) lo = mid + 1; else hi = mid; }
    int start = lo;
    hi = N_NODES;
    while (lo < hi) { int mid = (lo + hi) >> 1; if (batch[mid] < g + 1) lo = mid + 1; else hi = mid; }
    int end = lo;

    float acc = 0.0f;
    for (int n = start + sub; n < end; n += 4) acc += Z[n * LAT + k];
    red[sub][k] = acc;
    __syncthreads();
    if (sub == 0) {
        float s = red[0][k] + red[1][k] + red[2][k] + red[3][k];
        float zv = s / fmaxf((float)(end - start), 1.0f);
        z_graph[g * LAT + k] = zv;
        zg[k] = zv;
    }
    __syncthreads();
    if (tid < IN_CH) {
        float s = dec_b[tid];
#pragma unroll
        for (int kk = 0; kk < LAT; kk++) s = fmaf(zg[kk], dec_w[tid * LAT + kk], s);
        g_xg[g * IN_CH + tid] = s;
    }
}

__global__ void k_xhat(const int* __restrict__ batch, float* __restrict__ x_hat) {
    int idx = blockIdx.x * blockDim.x + threadIdx.x;  // < N_NODES*32
    int node = idx >> 5;
    int g = batch[node];
    ((float4*)x_hat)[idx] = ((const float4*)g_xg)[g * 32 + (idx & 31)];
}

// ============================================================
// a_hat = sigmoid(Z @ Z^T): symmetric, upper-tri tiles only.
// Direct orientation: streaming STG.64 from registers.
// Mirror orientation: smem transpose -> streaming STG.128.
// ============================================================
#define AH_TLD 132        // transpose staging pitch (float)
#define AH_NTILE 128
#define AH_NBLK (AH_NTILE * (AH_NTILE + 1) / 2)   // 8256

__global__ __launch_bounds__(256, 2) void k_ahat(const float* __restrict__ Z,
                                                 float* __restrict__ out) {
    extern __shared__ uint32_t smbuf[];
    uint32_t* As = smbuf;                 // [128][TLD]
    uint32_t* Bs = smbuf + 128 * TLD;     // [128][TLD]

    // decode linear block -> (bm<=bn): L = bn*(bn+1)/2 + bm
    int L = blockIdx.x;
    int bn = (int)((sqrtf(8.0f * (float)L + 1.0f) - 1.0f) * 0.5f);
    while ((bn + 1) * (bn + 2) / 2 <= L) bn++;
    while (bn * (bn + 1) / 2 > L) bn--;
    int bm = L - bn * (bn + 1) / 2;

    int tid = threadIdx.x;
    const float4* Z4 = (const float4*)Z;

#pragma unroll
    for (int it = 0; it < 8; ++it) {
        int idx = tid + it * 256;       // 2048 float4 per tile
        int row = idx >> 4, q = idx & 15;
        float4 va = Z4[(bm * 128 + row) * 16 + q];
        As[row * TLD + q * 4 + 0] = f2tf32(va.x);
        As[row * TLD + q * 4 + 1] = f2tf32(va.y);
        As[row * TLD + q * 4 + 2] = f2tf32(va.z);
        As[row * TLD + q * 4 + 3] = f2tf32(va.w);
        float4 vb = Z4[(bn * 128 + row) * 16 + q];
        Bs[row * TLD + q * 4 + 0] = f2tf32(vb.x);
        Bs[row * TLD + q * 4 + 1] = f2tf32(vb.y);
        Bs[row * TLD + q * 4 + 2] = f2tf32(vb.z);
        Bs[row * TLD + q * 4 + 3] = f2tf32(vb.w);
    }
    __syncthreads();

    int warp = tid >> 5, lane = tid & 31;
    int wm = (warp >> 2) * 64;
    int wn = (warp & 3) * 32;
    int gp = lane >> 2, tq = lane & 3;

    float acc[4][4][4];
#pragma unroll
    for (int mt = 0; mt < 4; mt++)
#pragma unroll
        for (int nt = 0; nt < 4; nt++)
#pragma unroll
            for (int r = 0; r < 4; r++) acc[mt][nt][r] = 0.0f;

#pragma unroll
    for (int ks = 0; ks < 8; ++ks) {
        int kb = ks * 8;
        uint32_t a[4][4], b[4][2];
#pragma unroll
        for (int mt = 0; mt < 4; ++mt) {
            int r0 = wm + mt * 16 + gp;
            a[mt][0] = As[r0 * TLD + kb + tq];
            a[mt][1] = As[(r0 + 8) * TLD + kb + tq];
            a[mt][2] = As[r0 * TLD + kb + tq + 4];
            a[mt][3] = As[(r0 + 8) * TLD + kb + tq + 4];
        }
#pragma unroll
        for (int nt = 0; nt < 4; ++nt) {
            int c0 = wn + nt * 8 + gp;
            b[nt][0] = Bs[c0 * TLD + kb + tq];
            b[nt][1] = Bs[c0 * TLD + kb + tq + 4];
        }
#pragma unroll
        for (int mt = 0; mt < 4; ++mt)
#pragma unroll
            for (int nt = 0; nt < 4; ++nt) MMA_TF32(acc[mt][nt], a[mt], b[nt]);
    }

    // sigmoid in registers, streaming STG.64 store of (bm,bn) tile
#pragma unroll
    for (int mt = 0; mt < 4; ++mt)
#pragma unroll
        for (int nt = 0; nt < 4; ++nt) {
#pragma unroll
            for (int r = 0; r < 4; ++r) acc[mt][nt][r] = fsig(acc[mt][nt][r]);
            int row = bm * 128 + wm + mt * 16 + gp;
            int col = bn * 128 + wn + nt * 8 + tq * 2;
            __stcs((float2*)(out + (size_t)row * N_NODES + col),
                   make_float2(acc[mt][nt][0], acc[mt][nt][1]));
            __stcs((float2*)(out + (size_t)(row + 8) * N_NODES + col),
                   make_float2(acc[mt][nt][2], acc[mt][nt][3]));
        }

    // mirror tile: transpose through smem (reuse As/Bs), streaming STG.128
    if (bm != bn) {
        __syncthreads();
        float* S = (float*)smbuf;         // [128][AH_TLD], 67584 B
#pragma unroll
        for (int mt = 0; mt < 4; ++mt)
#pragma unroll
            for (int nt = 0; nt < 4; ++nt) {
                int rl = wm + mt * 16 + gp;
                int cl = wn + nt * 8 + tq * 2;
                S[cl * AH_TLD + rl]           = acc[mt][nt][0];
                S[(cl + 1) * AH_TLD + rl]     = acc[mt][nt][1];
                S[cl * AH_TLD + rl + 8]       = acc[mt][nt][2];
                S[(cl + 1) * AH_TLD + rl + 8] = acc[mt][nt][3];
            }
        __syncthreads();
#pragma unroll
        for (int it = 0; it < 16; ++it) {
            int idx = tid + it * 256;     // 4096 float4
            int rt = idx >> 5, q = idx & 31;
            float4 w = *(const float4*)(S + rt * AH_TLD + q * 4);
            __stcs((float4*)(out + (size_t)(bn * 128 + rt) * N_NODES + bm * 128 + q * 4), w);
        }
    }
}

// ============================================================
// launch: pool+xhat forked to a side stream, overlapped with k_ahat
// ============================================================
extern "C" void kernel_launch(void* const* d_in, const int* in_sizes, int n_in,
                              void* d_out, int out_size) {
    const float* x     = (const float*)d_in[0];
    const int*   ei    = (const int*)d_in[1];    // int32
    const int*   batch = (const int*)d_in[2];    // int32, sorted
    const float* gcn_w = (const float*)d_in[3];
    const float* gcn_b = (const float*)d_in[4];
    const float* lin_w = (const float*)d_in[5];
    const float* lin_b = (const float*)d_in[6];
    const float* dec_w = (const float*)d_in[7];
    const float* dec_b = (const float*)d_in[8];

    float* out     = (float*)d_out;
    float* z_node  = out;
    float* z_graph = out + 1048576;
    float* x_hat   = out + 1049600;
    float* a_hat   = out + 3146752;

    static cudaStream_t s2 = nullptr;
    static cudaEvent_t eFork = nullptr, eJoin = nullptr;
    if (!s2) {
        cudaStreamCreateWithFlags(&s2, cudaStreamNonBlocking);
        cudaEventCreateWithFlags(&eFork, cudaEventDisableTiming);
        cudaEventCreateWithFlags(&eJoin, cudaEventDisableTiming);
        const int SM2T = 2 * 128 * TLD * 4;
        const int SMG2 = (128 + 64) * TLD * 4;
        cudaFuncSetAttribute(k_ahat,  cudaFuncAttributeMaxDynamicSharedMemorySize, SM2T);
        cudaFuncSetAttribute(k_gemm1, cudaFuncAttributeMaxDynamicSharedMemorySize, SM2T);
        cudaFuncSetAttribute(k_gemm2, cudaFuncAttributeMaxDynamicSharedMemorySize, SMG2);
    }
    const int SMEM_2T = 2 * 128 * TLD * 4;       // 69632 B
    const int SMEM_G2 = (128 + 64) * TLD * 4;    // 52224 B

    k_init<<<64, 256>>>();
    k_degree<<<1024, 256>>>(ei);
    k_scale<<<2048, 256>>>((const float4*)x);
    k_scatter<<<32768, 256>>>(ei, (const float4*)x);
    k_gemm1<<<dim3(2, 128), 256, SMEM_2T>>>(gcn_w, gcn_b);
    k_gemm2<<<128, 256, SMEM_G2>>>(lin_w, lin_b, z_node);

    // fork: pool + xhat run on s2 concurrently with k_ahat on the main stream
    cudaEventRecord(eFork, 0);
    cudaStreamWaitEvent(s2, eFork, 0);
    k_poolfused<<<N_GRAPHS, 256, 0, s2>>>(z_node, batch, z_graph, dec_w, dec_b);
    k_xhat<<<2048, 256, 0, s2>>>(batch, x_hat);
    cudaEventRecord(eJoin, s2);

    k_ahat<<<AH_NBLK, 256, SMEM_2T>>>(z_node, a_hat);

    // join
    cudaStreamWaitEvent(0, eJoin, 0);
}